// round 12
// baseline (speedup 1.0000x reference)
#include <cuda_runtime.h>
#include <cuda_bf16.h>
#include <cstdint>

// pooled[i][j] = 1.0 if any k in [j-25, j+25] (in-range) has |in[i]-w[k]| < 0.1
// N=1024, M=262144 -> 1 GiB fp32 output; HBM write roofline target.
//
// R12 = R11 with WPT 16->8 and FOUR-row packing:
//  - 8 weights/thread (4 packed f32x2 pairs, 8 regs) -> regs ~40, 6 blocks/SM
//    (48 warps, 75% occ) vs 5 (56%): more latency-hiding for the store stream
//    (R11 showed nothing saturated -> latency-bound residual).
//  - masks are 8-bit; 4 rows pack into one 32-bit reg: one set of neighbor
//    shuffles (8) + emit shuffles (2) serves 4 rows.
//  - radius-25 window spans +/-4 neighbor 8-bit words; halo bytes come from
//    the 32-bit edge ballots.

#define THREADS 256
#define WPT 8                        // pooled bits per thread
#define SEG 256                      // columns per warp (32 lanes * 8)
#define CHUNK (THREADS * WPT)        // 2048 columns per block
#define ROWS_PER_BLOCK 8
#define THRESH 0.1f
#define OOR_VAL 3.0e38f              // sentinel == -inf pad (never within 0.1)
#define FULL 0xFFFFFFFFu

// mask bit b (0..7) = (vi - w[b])^2 < 0.01
__device__ __forceinline__ unsigned mask8_sq(unsigned long long vv,
                                             const unsigned long long* nwp,
                                             unsigned long long c2)
{
    unsigned m = 0;
    #pragma unroll
    for (int k = 3; k >= 0; --k) {
        unsigned long long d, s;
        asm("add.rn.f32x2 %0, %1, %2;" : "=l"(d) : "l"(vv), "l"(nwp[k]));
        asm("fma.rn.f32x2 %0, %1, %1, %2;" : "=l"(s) : "l"(d), "l"(c2));
        m = __funnelshift_l((unsigned)(s >> 32), m, 1);   // weight 2k+1
        m = __funnelshift_l((unsigned)s,         m, 1);   // weight 2k
    }
    return m & 0xFFu;
}

__global__ __launch_bounds__(THREADS, 6)
void cll_pool_kernel(const float* __restrict__ in_feat,
                     const float* __restrict__ weights,
                     float* __restrict__ out,
                     int N, int M)
{
    const int t = threadIdx.x;
    const int lane = t & 31;
    const int warp = t >> 5;
    const int segbase = blockIdx.x * CHUNK + warp * SEG;

    // ---- one-time: this thread's 8 weights -> 4 packed negated pairs ----
    unsigned long long nwp[4];
    {
        const int g0 = segbase + lane * WPT;
        float wv[8];
        if (g0 + WPT <= M) {
            const float4* wp = reinterpret_cast<const float4*>(weights + g0);
            float4 q0 = wp[0], q1 = wp[1];
            wv[0]=q0.x; wv[1]=q0.y; wv[2]=q0.z; wv[3]=q0.w;
            wv[4]=q1.x; wv[5]=q1.y; wv[6]=q1.z; wv[7]=q1.w;
        } else {
            #pragma unroll
            for (int b = 0; b < 8; ++b) {
                int gg = g0 + b;
                wv[b] = (gg < M) ? weights[gg] : OOR_VAL;
            }
        }
        #pragma unroll
        for (int k = 0; k < 4; ++k) {
            unsigned lo = __float_as_uint(-wv[2*k]);
            unsigned hi = __float_as_uint(-wv[2*k+1]);
            nwp[k] = ((unsigned long long)hi << 32) | lo;
        }
    }
    // per-lane halo weights (32 cols each side of the warp segment)
    float hwl, hwr;
    {
        int gl = segbase - 32 + lane;          // cols [segbase-32, segbase)
        int gr = segbase + SEG + lane;         // cols [segbase+SEG, segbase+SEG+32)
        hwl = (gl >= 0 && gl < M) ? __ldg(weights + gl) : OOR_VAL;
        hwr = (gr < M)            ? __ldg(weights + gr) : OOR_VAL;
    }

    const unsigned long long c2 =
        ((unsigned long long)__float_as_uint(-0.01f) << 32) | __float_as_uint(-0.01f);

    const int row0 = blockIdx.y * ROWS_PER_BLOCK;
    const int shamt = (lane & 1) * 4;          // nibble within owner's 8 pooled bits
    const int srcbase = lane >> 1;             // owner-lane offset within emit step

    #pragma unroll 1
    for (int r = 0; r < ROWS_PER_BLOCK; r += 4) {
        int ii[4];
        float v[4];
        #pragma unroll
        for (int x = 0; x < 4; ++x) {
            int i = row0 + r + x;
            ii[x] = (i < N) ? i : (N - 1);
            v[x] = __ldg(&in_feat[ii[x]]);
        }

        // ---- four 8-bit mask words, packed (row x in byte x) ----
        unsigned mm = 0;
        unsigned hl[4], hr[4];
        #pragma unroll
        for (int x = 0; x < 4; ++x) {
            const unsigned long long vvx =
                ((unsigned long long)__float_as_uint(v[x]) << 32) | __float_as_uint(v[x]);
            mm |= mask8_sq(vvx, nwp, c2) << (8 * x);
            hl[x] = __ballot_sync(FULL, fabsf(v[x] - hwl) < THRESH);
            hr[x] = __ballot_sync(FULL, fabsf(v[x] - hwr) < THRESH);
        }

        // ---- one set of neighbor shuffles serves all 4 rows ----
        unsigned wm[4], wp[4];
        #pragma unroll
        for (int q = 1; q <= 4; ++q) {
            wm[q-1] = __shfl_up_sync(FULL, mm, q);
            wp[q-1] = __shfl_down_sync(FULL, mm, q);
        }
        // halo fixups: word w[-q] for lane<q comes from hl bits [32-(q-lane)*8, +8)
        if (lane < 4) {
            #pragma unroll
            for (int q = 1; q <= 4; ++q) {
                if (lane < q) {
                    const int sh = 32 - (q - lane) * 8;
                    wm[q-1] =  ((hl[0] >> sh) & 0xFFu)
                            | (((hl[1] >> sh) & 0xFFu) << 8)
                            | (((hl[2] >> sh) & 0xFFu) << 16)
                            | (((hl[3] >> sh) & 0xFFu) << 24);
                }
            }
        }
        // word w[+q] for lane+q>=32 comes from hr bits [(lane+q-32)*8, +8)
        if (lane >= 28) {
            #pragma unroll
            for (int q = 1; q <= 4; ++q) {
                if (lane + q >= 32) {
                    const int sh = (lane + q - 32) * 8;
                    wp[q-1] =  ((hr[0] >> sh) & 0xFFu)
                            | (((hr[1] >> sh) & 0xFFu) << 8)
                            | (((hr[2] >> sh) & 0xFFu) << 16)
                            | (((hr[3] >> sh) & 0xFFu) << 24);
                }
            }
        }

        // ---- per-row window assembly + width-51 dilation ----
        unsigned pp = 0;
        #pragma unroll
        for (int x = 0; x < 4; ++x) {
            const int sh8 = 8 * x;
            const unsigned a4 = (wm[3] >> sh8) & 0xFFu;
            const unsigned a3 = (wm[2] >> sh8) & 0xFFu;
            const unsigned a2 = (wm[1] >> sh8) & 0xFFu;
            const unsigned a1 = (wm[0] >> sh8) & 0xFFu;
            const unsigned a0 = (mm    >> sh8) & 0xFFu;
            const unsigned b1 = (wp[0] >> sh8) & 0xFFu;
            const unsigned b2 = (wp[1] >> sh8) & 0xFFu;
            const unsigned b3 = (wp[2] >> sh8) & 0xFFu;
            const unsigned b4 = (wp[3] >> sh8) & 0xFFu;
            // lo covers [base-32, base+32), hi covers [base-24, base+40)
            unsigned long long lo =  (unsigned long long)(a4 | (a3<<8) | (a2<<16) | (a1<<24))
                                  | ((unsigned long long)(a0 | (b1<<8) | (b2<<16) | (b3<<24)) << 32);
            unsigned long long hi =  (unsigned long long)(a3 | (a2<<8) | (a1<<16) | (a0<<24))
                                  | ((unsigned long long)(b1 | (b2<<8) | (b3<<16) | (b4<<24)) << 32);
            // left-dilate lo by 25, right-dilate hi by 25
            lo |= lo << 1;  lo |= lo << 2;  lo |= lo << 4;  lo |= lo << 8;  lo |= lo << 10;
            hi |= hi >> 1;  hi |= hi >> 2;  hi |= hi >> 4;  hi |= hi >> 8;  hi |= hi >> 10;
            // pooled[t] = lo'[t+32] | hi'[t+24]
            const unsigned p = ((unsigned)(lo >> 32) | (unsigned)(hi >> 24)) & 0xFFu;
            pp |= p << sh8;
        }

        // ---- emit: 2 shuffles serve 4 rows x 2 dense 512B steps ----
        // step s: lane t writes cols s*128 + t*4; owner lane s*16 + t/2, nibble t%2
        #pragma unroll
        for (int s = 0; s < 2; ++s) {
            const unsigned src = __shfl_sync(FULL, pp, s * 16 + srcbase);
            #pragma unroll
            for (int x = 0; x < 4; ++x) {
                const unsigned bits = src >> (8 * x + shamt);
                float4 q;
                q.x = __uint_as_float((bits & 1u) * 0x3F800000u);
                q.y = __uint_as_float((bits & 2u) * 0x1FC00000u);
                q.z = __uint_as_float((bits & 4u) * 0x0FE00000u);
                q.w = __uint_as_float((bits & 8u) * 0x07F00000u);
                float* wrow = out + (size_t)ii[x] * (size_t)M + segbase + s * 128;
                __stcs(reinterpret_cast<float4*>(wrow) + lane, q);
            }
        }
    }
}

extern "C" void kernel_launch(void* const* d_in, const int* in_sizes, int n_in,
                              void* d_out, int out_size)
{
    const float* in_feat = (const float*)d_in[0];   // 1024 elements
    const float* weights = (const float*)d_in[1];   // 262144 elements
    float* out = (float*)d_out;

    const int N = in_sizes[0];
    const int M = in_sizes[1];

    dim3 grid((M + CHUNK - 1) / CHUNK, (N + ROWS_PER_BLOCK - 1) / ROWS_PER_BLOCK);
    cll_pool_kernel<<<grid, THREADS>>>(in_feat, weights, out, N, M);
}

// round 13
// speedup vs baseline: 1.3087x; 1.3087x over previous
#include <cuda_runtime.h>
#include <cuda_bf16.h>
#include <cstdint>

// pooled[i][j] = 1.0 if any k in [j-25, j+25] (in-range) has |in[i]-w[k]| < 0.1
// N=1024, M=262144 -> 1 GiB fp32 output; HBM write roofline target.
//
// R13 = R11 EXACTLY (best ALU/MIO balance: 145.9us, DRAM 88.4%) with ONE
// change: __launch_bounds__(256, 6) to force 42 regs and a 6th resident
// block per SM (40 -> 48 warps). R12 proved the occupancy lever works
// (56->70%) but paid 2x ALU for it at WPT=8; this buys occupancy with
// register pressure alone, keeping WPT=16's cheap per-output path.

#define THREADS 256
#define WPT 16                       // pooled bits per thread
#define SEG 512                      // columns per warp
#define CHUNK (THREADS * WPT)        // 4096 columns per block
#define ROWS_PER_BLOCK 8
#define THRESH 0.1f
#define OOR_VAL 3.0e38f              // sentinel == -inf pad (never within 0.1)

// mask bit b (0..15) = (vi - w[b])^2 < 0.01
__device__ __forceinline__ unsigned mask16_sq(unsigned long long vv,
                                              const unsigned long long* nwp,
                                              unsigned long long c2)
{
    unsigned m = 0;
    #pragma unroll
    for (int k = 7; k >= 0; --k) {
        unsigned long long d, s;
        asm("add.rn.f32x2 %0, %1, %2;" : "=l"(d) : "l"(vv), "l"(nwp[k]));
        asm("fma.rn.f32x2 %0, %1, %1, %2;" : "=l"(s) : "l"(d), "l"(c2));
        m = __funnelshift_l((unsigned)(s >> 32), m, 1);   // weight 2k+1
        m = __funnelshift_l((unsigned)s,         m, 1);   // weight 2k
    }
    return m & 0xFFFFu;
}

__global__ __launch_bounds__(THREADS, 6)
void cll_pool_kernel(const float* __restrict__ in_feat,
                     const float* __restrict__ weights,
                     float* __restrict__ out,
                     int N, int M)
{
    const int t = threadIdx.x;
    const int lane = t & 31;
    const int warp = t >> 5;
    const int segbase = blockIdx.x * CHUNK + warp * SEG;

    // ---- one-time: this thread's 16 weights -> 8 packed negated pairs ----
    unsigned long long nwp[8];
    {
        const int g0 = segbase + lane * WPT;
        float wv[16];
        if (g0 + WPT <= M) {
            const float4* wp = reinterpret_cast<const float4*>(weights + g0);
            #pragma unroll
            for (int g = 0; g < 4; ++g) {
                float4 q = wp[g];
                wv[4*g+0] = q.x; wv[4*g+1] = q.y; wv[4*g+2] = q.z; wv[4*g+3] = q.w;
            }
        } else {
            #pragma unroll
            for (int b = 0; b < 16; ++b) {
                int gg = g0 + b;
                wv[b] = (gg < M) ? weights[gg] : OOR_VAL;
            }
        }
        #pragma unroll
        for (int k = 0; k < 8; ++k) {
            unsigned lo = __float_as_uint(-wv[2*k]);
            unsigned hi = __float_as_uint(-wv[2*k+1]);
            nwp[k] = ((unsigned long long)hi << 32) | lo;
        }
    }
    // per-lane halo weights (32 cols each side of segment)
    float hwl, hwr;
    {
        int gl = segbase - 32 + lane;
        int gr = segbase + SEG + lane;
        hwl = (gl >= 0 && gl < M) ? __ldg(weights + gl) : OOR_VAL;
        hwr = (gr < M)            ? __ldg(weights + gr) : OOR_VAL;
    }

    const unsigned long long c2 =
        ((unsigned long long)__float_as_uint(-0.01f) << 32) | __float_as_uint(-0.01f);

    const int row0 = blockIdx.y * ROWS_PER_BLOCK;
    const int shamt = (lane & 3) * 4;
    const int srcbase = lane >> 2;

    #pragma unroll 1
    for (int r = 0; r < ROWS_PER_BLOCK; r += 2) {
        int i0 = row0 + r;     if (i0 >= N) i0 = N - 1;
        int i1 = row0 + r + 1; if (i1 >= N) i1 = N - 1;
        const float v0 = __ldg(&in_feat[i0]);
        const float v1 = __ldg(&in_feat[i1]);

        // ---- two 16-bit mask words, packed ----
        const unsigned long long vv0 =
            ((unsigned long long)__float_as_uint(v0) << 32) | __float_as_uint(v0);
        const unsigned long long vv1 =
            ((unsigned long long)__float_as_uint(v1) << 32) | __float_as_uint(v1);
        const unsigned mm = mask16_sq(vv0, nwp, c2) | (mask16_sq(vv1, nwp, c2) << 16);

        const unsigned hl0 = __ballot_sync(0xFFFFFFFFu, fabsf(v0 - hwl) < THRESH);
        const unsigned hr0 = __ballot_sync(0xFFFFFFFFu, fabsf(v0 - hwr) < THRESH);
        const unsigned hl1 = __ballot_sync(0xFFFFFFFFu, fabsf(v1 - hwl) < THRESH);
        const unsigned hr1 = __ballot_sync(0xFFFFFFFFu, fabsf(v1 - hwr) < THRESH);

        // ---- ONE set of neighbor shuffles for both rows ----
        unsigned wm1 = __shfl_up_sync(0xFFFFFFFFu, mm, 1);
        unsigned wm2 = __shfl_up_sync(0xFFFFFFFFu, mm, 2);
        unsigned wp1 = __shfl_down_sync(0xFFFFFFFFu, mm, 1);
        unsigned wp2 = __shfl_down_sync(0xFFFFFFFFu, mm, 2);
        if (lane == 0) {
            wm1 = (hl0 >> 16) | (hl1 & 0xFFFF0000u);
            wm2 = (hl0 & 0xFFFFu) | (hl1 << 16);
        }
        if (lane == 1)  { wm2 = (hl0 >> 16) | (hl1 & 0xFFFF0000u); }
        if (lane == 31) {
            wp1 = (hr0 & 0xFFFFu) | (hr1 << 16);
            wp2 = (hr0 >> 16) | (hr1 & 0xFFFF0000u);
        }
        if (lane == 30) { wp2 = (hr0 & 0xFFFFu) | (hr1 << 16); }

        // ---- per-row dilation, pooled words packed ----
        unsigned pp = 0;
        #pragma unroll
        for (int x = 0; x < 2; ++x) {
            const unsigned a2 = (wm2 >> (16 * x)) & 0xFFFFu;
            const unsigned a1 = (wm1 >> (16 * x)) & 0xFFFFu;
            const unsigned a0 = (mm  >> (16 * x)) & 0xFFFFu;
            const unsigned b1 = (wp1 >> (16 * x)) & 0xFFFFu;
            const unsigned b2 = (wp2 >> (16 * x)) & 0xFFFFu;
            unsigned long long lo =  (unsigned long long)a2
                                  | ((unsigned long long)a1 << 16)
                                  | ((unsigned long long)a0 << 32)
                                  | ((unsigned long long)b1 << 48);
            unsigned long long hi =  (unsigned long long)a1
                                  | ((unsigned long long)a0 << 16)
                                  | ((unsigned long long)b1 << 32)
                                  | ((unsigned long long)b2 << 48);
            hi |= hi >> 1;  hi |= hi >> 2;  hi |= hi >> 4;  hi |= hi >> 8;  hi |= hi >> 10;
            lo |= lo << 1;  lo |= lo << 2;  lo |= lo << 4;  lo |= lo << 8;  lo |= lo << 10;
            const unsigned p = ((unsigned)(lo >> 32) | (unsigned)(hi >> 16)) & 0xFFFFu;
            pp |= p << (16 * x);
        }

        // ---- emit: ONE set of 4 shuffles feeds both rows' dense stores ----
        float* w0 = out + (size_t)i0 * (size_t)M + segbase;
        float* w1 = out + (size_t)i1 * (size_t)M + segbase;
        #pragma unroll
        for (int s = 0; s < 4; ++s) {
            const unsigned src = __shfl_sync(0xFFFFFFFFu, pp, s * 8 + srcbase);
            const unsigned b0 = src >> shamt;          // row i0 nibble
            const unsigned b1 = src >> (shamt + 16);   // row i1 nibble
            float4 q0, q1;
            q0.x = __uint_as_float((b0 & 1u) * 0x3F800000u);
            q0.y = __uint_as_float((b0 & 2u) * 0x1FC00000u);
            q0.z = __uint_as_float((b0 & 4u) * 0x0FE00000u);
            q0.w = __uint_as_float((b0 & 8u) * 0x07F00000u);
            q1.x = __uint_as_float((b1 & 1u) * 0x3F800000u);
            q1.y = __uint_as_float((b1 & 2u) * 0x1FC00000u);
            q1.z = __uint_as_float((b1 & 4u) * 0x0FE00000u);
            q1.w = __uint_as_float((b1 & 8u) * 0x07F00000u);
            __stcs(reinterpret_cast<float4*>(w0 + s * 128) + lane, q0);
            __stcs(reinterpret_cast<float4*>(w1 + s * 128) + lane, q1);
        }
    }
}

extern "C" void kernel_launch(void* const* d_in, const int* in_sizes, int n_in,
                              void* d_out, int out_size)
{
    const float* in_feat = (const float*)d_in[0];   // 1024 elements
    const float* weights = (const float*)d_in[1];   // 262144 elements
    float* out = (float*)d_out;

    const int N = in_sizes[0];
    const int M = in_sizes[1];

    dim3 grid((M + CHUNK - 1) / CHUNK, (N + ROWS_PER_BLOCK - 1) / ROWS_PER_BLOCK);
    cll_pool_kernel<<<grid, THREADS>>>(in_feat, weights, out, N, M);
}